// round 4
// baseline (speedup 1.0000x reference)
#include <cuda_runtime.h>
#include <cuda_bf16.h>
#include <math_constants.h>

#define NEG_INF_VAL (-1.0e9f)
#define P_PATCHES 1024
#define MAX_BS 16
#define PPC 8     // patches per CTA chunk (token range is contiguous by sortedness)

__device__ int g_starts[MAX_BS * (P_PATCHES + 1)];

__global__ void __launch_bounds__(P_PATCHES)
bounds_kernel(const int* __restrict__ pids, int seq)
{
    extern __shared__ int s_pid[];
    const int b = blockIdx.x;
    const int* pid_b = pids + (long)b * seq;

    for (int t = threadIdx.x; t < seq; t += blockDim.x)
        s_pid[t] = pid_b[t];
    __syncthreads();

    const int p = threadIdx.x;
    int lo = 0, hi = seq;
    while (lo < hi) {
        int mid = (lo + hi) >> 1;
        if (s_pid[mid] < p) lo = mid + 1; else hi = mid;
    }
    g_starts[b * (P_PATCHES + 1) + p] = lo;
    if (p == 0) g_starts[b * (P_PATCHES + 1) + P_PATCHES] = seq;
}

__device__ __forceinline__ void upd(float v, float& m1, float& m2) {
    if (v > m1) { m2 = m1; m1 = v; }
    else if (v < m1) { m2 = fmaxf(m2, v); }
    // v == m1: duplicate of max -> fully masked by the reference; skip.
}

__device__ __forceinline__ void upd4(const float4& v, float4& m1, float4& m2) {
    upd(v.x, m1.x, m2.x);
    upd(v.y, m1.y, m2.y);
    upd(v.z, m1.z, m2.z);
    upd(v.w, m1.w, m2.w);
}

// Finalize patch pi: cnt tokens accumulated into (m1,m2); write and reset.
#define FLUSH()                                                              \
    do {                                                                     \
        int cnt = nb - pstart;                                               \
        float4 r;                                                            \
        if (cnt == 0) {                                                      \
            r = make_float4(0.f, 0.f, 0.f, 0.f);                             \
        } else if (cnt == 1) {                                               \
            r = m1;                                                          \
        } else {                                                             \
            float s2x = (m2.x == -CUDART_INF_F) ? NEG_INF_VAL : m2.x;        \
            float s2y = (m2.y == -CUDART_INF_F) ? NEG_INF_VAL : m2.y;        \
            float s2z = (m2.z == -CUDART_INF_F) ? NEG_INF_VAL : m2.z;        \
            float s2w = (m2.w == -CUDART_INF_F) ? NEG_INF_VAL : m2.w;        \
            r = make_float4((m1.x + s2x) * 0.5f, (m1.y + s2y) * 0.5f,        \
                            (m1.z + s2z) * 0.5f, (m1.w + s2w) * 0.5f);       \
        }                                                                    \
        *(float4*)(ob + (long)pi * E) = r;                                   \
        m1 = make_float4(-CUDART_INF_F, -CUDART_INF_F, -CUDART_INF_F,        \
                         -CUDART_INF_F);                                     \
        m2 = m1;                                                             \
    } while (0)

__global__ void __launch_bounds__(128)
topk_mean_kernel(const float* __restrict__ h,
                 float* __restrict__ out,
                 int seq, int E)
{
    __shared__ int sb[PPC + 1];
    const int chunk = blockIdx.x;
    const int b = blockIdx.y;
    const int p0 = chunk * PPC;

    if (threadIdx.x <= PPC)
        sb[threadIdx.x] = g_starts[b * (P_PATCHES + 1) + p0 + threadIdx.x];
    __syncthreads();

    const int e = threadIdx.x * 4;
    const float* hb = h + (long)b * seq * E + e;
    float* ob = out + ((long)b * P_PATCHES + p0) * E + e;

    const int t0 = sb[0];
    const int tend = sb[PPC];

    int pi = 0;
    int pstart = t0;
    int nb = sb[1];  // next patch boundary, register-cached

    float4 m1 = make_float4(-CUDART_INF_F, -CUDART_INF_F, -CUDART_INF_F, -CUDART_INF_F);
    float4 m2 = m1;

    int t = t0;
    // Main loop: 4 independent streaming loads per iteration (MLP=4/thread).
    for (; t + 4 <= tend; t += 4) {
        float4 v0 = *(const float4*)(hb + (long)(t + 0) * E);
        float4 v1 = *(const float4*)(hb + (long)(t + 1) * E);
        float4 v2 = *(const float4*)(hb + (long)(t + 2) * E);
        float4 v3 = *(const float4*)(hb + (long)(t + 3) * E);
#pragma unroll
        for (int j = 0; j < 4; ++j) {
            while (t + j >= nb) { FLUSH(); ++pi; pstart = nb; nb = sb[pi + 1]; }
            float4 v = (j == 0) ? v0 : (j == 1) ? v1 : (j == 2) ? v2 : v3;
            upd4(v, m1, m2);
        }
    }
    for (; t < tend; ++t) {
        float4 v = *(const float4*)(hb + (long)t * E);
        while (t >= nb) { FLUSH(); ++pi; pstart = nb; nb = sb[pi + 1]; }
        upd4(v, m1, m2);
    }
    // Flush the last accumulated patch + any trailing empty patches.
    while (pi < PPC) {
        FLUSH();
        ++pi;
        if (pi < PPC) { pstart = nb; nb = sb[pi + 1]; }
    }
}

extern "C" void kernel_launch(void* const* d_in, const int* in_sizes, int n_in,
                              void* d_out, int out_size)
{
    const float* h    = (const float*)d_in[0];
    const int*   pids = (const int*)d_in[1];
    float*       out  = (float*)d_out;

    const int total_tok = in_sizes[1];           // bs * seq
    const int E  = in_sizes[0] / total_tok;      // 512
    const int bs = out_size / (P_PATCHES * E);   // 8
    const int seq = total_tok / bs;              // 4096

    bounds_kernel<<<bs, P_PATCHES, seq * sizeof(int)>>>(pids, seq);

    dim3 grid(P_PATCHES / PPC, bs);              // (128, 8) = 1024 CTAs
    dim3 block(E / 4);                           // 128 threads, 4 dims (float4) each
    topk_mean_kernel<<<grid, block>>>(h, out, seq, E);
}

// round 5
// speedup vs baseline: 1.1667x; 1.1667x over previous
#include <cuda_runtime.h>
#include <cuda_bf16.h>
#include <math_constants.h>

#define NEG_INF_VAL (-1.0e9f)
#define P_PATCHES 1024
#define MAX_BS 16
#define PPC 2     // patches per CTA (contiguous token range by sortedness)

__device__ int g_starts[MAX_BS * (P_PATCHES + 1)];

__global__ void __launch_bounds__(P_PATCHES)
bounds_kernel(const int* __restrict__ pids, int seq)
{
    extern __shared__ int s_pid[];
    const int b = blockIdx.x;
    const int* pid_b = pids + (long)b * seq;

    for (int t = threadIdx.x; t < seq; t += blockDim.x)
        s_pid[t] = pid_b[t];
    __syncthreads();

    const int p = threadIdx.x;
    int lo = 0, hi = seq;
    while (lo < hi) {
        int mid = (lo + hi) >> 1;
        if (s_pid[mid] < p) lo = mid + 1; else hi = mid;
    }
    g_starts[b * (P_PATCHES + 1) + p] = lo;
    if (p == 0) g_starts[b * (P_PATCHES + 1) + P_PATCHES] = seq;
}

// Branchless top-2 with duplicate-of-max exclusion (reference masks ALL copies
// of the max): if v==m1 the candidate for m2 is -inf (no-op).
__device__ __forceinline__ void upd(float v, float& m1, float& m2) {
    float lo = (v == m1) ? -CUDART_INF_F : fminf(v, m1);
    m2 = fmaxf(m2, lo);
    m1 = fmaxf(m1, v);
}

__device__ __forceinline__ void upd4(const float4& v, float4& m1, float4& m2) {
    upd(v.x, m1.x, m2.x);
    upd(v.y, m1.y, m2.y);
    upd(v.z, m1.z, m2.z);
    upd(v.w, m1.w, m2.w);
}

#define FLUSH()                                                              \
    do {                                                                     \
        int cnt = nb - pstart;                                               \
        float4 r;                                                            \
        if (cnt == 0) {                                                      \
            r = make_float4(0.f, 0.f, 0.f, 0.f);                             \
        } else if (cnt == 1) {                                               \
            r = m1;                                                          \
        } else {                                                             \
            float s2x = (m2.x == -CUDART_INF_F) ? NEG_INF_VAL : m2.x;        \
            float s2y = (m2.y == -CUDART_INF_F) ? NEG_INF_VAL : m2.y;        \
            float s2z = (m2.z == -CUDART_INF_F) ? NEG_INF_VAL : m2.z;        \
            float s2w = (m2.w == -CUDART_INF_F) ? NEG_INF_VAL : m2.w;        \
            r = make_float4((m1.x + s2x) * 0.5f, (m1.y + s2y) * 0.5f,        \
                            (m1.z + s2z) * 0.5f, (m1.w + s2w) * 0.5f);       \
        }                                                                    \
        *(float4*)(ob + (long)pi * E) = r;                                   \
        m1 = make_float4(-CUDART_INF_F, -CUDART_INF_F, -CUDART_INF_F,        \
                         -CUDART_INF_F);                                     \
        m2 = m1;                                                             \
    } while (0)

template <int E>
__global__ void __launch_bounds__(128)
topk_mean_kernel(const float* __restrict__ h,
                 float* __restrict__ out,
                 int seq)
{
    __shared__ int sb[PPC + 1];
    const int chunk = blockIdx.x;
    const int b = blockIdx.y;
    const int p0 = chunk * PPC;

    if (threadIdx.x <= PPC)
        sb[threadIdx.x] = g_starts[b * (P_PATCHES + 1) + p0 + threadIdx.x];
    __syncthreads();

    const int e = threadIdx.x * 4;
    const float* hb = h + (long)b * seq * E + e;
    float* ob = out + ((long)b * P_PATCHES + p0) * E + e;

    const int t0 = sb[0];
    const int tend = sb[PPC];

    int pi = 0;
    int pstart = t0;
    int nb = sb[1];

    float4 m1 = make_float4(-CUDART_INF_F, -CUDART_INF_F, -CUDART_INF_F, -CUDART_INF_F);
    float4 m2 = m1;

    int t = t0;
    const float* hp = hb + (long)t0 * E;
    // 4 independent streaming loads per iteration; E is a compile-time
    // constant so the +E,+2E,+3E offsets fold into the LDG immediates.
    for (; t + 4 <= tend; t += 4, hp += 4 * E) {
        float4 v0 = *(const float4*)(hp);
        float4 v1 = *(const float4*)(hp + E);
        float4 v2 = *(const float4*)(hp + 2 * E);
        float4 v3 = *(const float4*)(hp + 3 * E);
#pragma unroll
        for (int j = 0; j < 4; ++j) {
            while (t + j >= nb) { FLUSH(); ++pi; pstart = nb; nb = sb[pi + 1]; }
            float4 v = (j == 0) ? v0 : (j == 1) ? v1 : (j == 2) ? v2 : v3;
            upd4(v, m1, m2);
        }
    }
    for (; t < tend; ++t, hp += E) {
        float4 v = *(const float4*)(hp);
        while (t >= nb) { FLUSH(); ++pi; pstart = nb; nb = sb[pi + 1]; }
        upd4(v, m1, m2);
    }
    while (pi < PPC) {
        FLUSH();
        ++pi;
        if (pi < PPC) { pstart = nb; nb = sb[pi + 1]; }
    }
}

extern "C" void kernel_launch(void* const* d_in, const int* in_sizes, int n_in,
                              void* d_out, int out_size)
{
    const float* h    = (const float*)d_in[0];
    const int*   pids = (const int*)d_in[1];
    float*       out  = (float*)d_out;

    const int total_tok = in_sizes[1];           // bs * seq
    const int E  = in_sizes[0] / total_tok;      // 512
    const int bs = out_size / (P_PATCHES * E);   // 8
    const int seq = total_tok / bs;              // 4096

    bounds_kernel<<<bs, P_PATCHES, seq * sizeof(int)>>>(pids, seq);

    dim3 grid(P_PATCHES / PPC, bs);              // (512, 8) = 4096 CTAs
    dim3 block(128);                             // 128 threads, 4 dims (float4) each
    if (E == 512) {
        topk_mean_kernel<512><<<grid, block>>>(h, out, seq);
    } else if (E == 256) {
        dim3 blk(64);
        topk_mean_kernel<256><<<grid, blk>>>(h, out, seq);
    } else if (E == 1024) {
        dim3 blk(256);
        topk_mean_kernel<1024><<<grid, blk>>>(h, out, seq);
    }
}